// round 13
// baseline (speedup 1.0000x reference)
#include <cuda_runtime.h>
#include <cuda_fp16.h>
#include <math.h>
#include <stdint.h>

// Problem shape (fixed by dataset)
#define B 4
#define S 2048
#define H 1024
#define NCH 32          // chunks of 64 t per batch
#define CHW 64

// Scratch (device globals: no allocation allowed in kernel_launch)
__device__ __align__(16) __half g_valueh[B * S * H];  // value projection (fp16)
__device__ __align__(16) __half g_Ah[B * S * H];      // hs  as fp16
__device__ __align__(16) __half g_Bh[H * H];          // W   as fp16
__device__ float g_A[B * S];        // (x.U + U_H) / 8   per row
__device__ float g_C[B * S];        // x.V + V_H         per row
__device__ float g_m[B * S];        // row max of scores
__device__ float g_csort[B * S];    // c sorted ascending per batch
__device__ int   g_cperm[B * S];    // original t index per sorted position
__device__ float g_masksort[B * S]; // mask[cperm[j]]
__device__ int   g_sperm[B * S];    // s rows sorted by a per batch
__device__ float g_chmin[B * NCH];
__device__ float g_chmax[B * NCH];
__device__ float g_chmmax[B * NCH];

// ---------------------------------------------------------------------------
// PTX helpers
// ---------------------------------------------------------------------------
__device__ __forceinline__ uint32_t smem_u32(const void* p) {
    uint32_t a;
    asm("{ .reg .u64 t; cvta.to.shared.u64 t, %1; cvt.u32.u64 %0, t; }"
        : "=r"(a) : "l"(p));
    return a;
}
#define CPASYNC16(dst, src) \
    asm volatile("cp.async.cg.shared.global [%0], [%1], 16;" :: "r"(dst), "l"(src))
#define CPCOMMIT() asm volatile("cp.async.commit_group;" ::: "memory")
#define CPWAIT1()  asm volatile("cp.async.wait_group 1;" ::: "memory")
#define CPWAIT0()  asm volatile("cp.async.wait_group 0;" ::: "memory")
#define LDSM4(R, addr)                                                        \
    asm volatile("ldmatrix.sync.aligned.m8n8.x4.shared.b16 {%0,%1,%2,%3}, [%4];" \
                 : "=r"((R)[0]), "=r"((R)[1]), "=r"((R)[2]), "=r"((R)[3])     \
                 : "r"(addr))
#define LDSM4T(R, addr)                                                       \
    asm volatile("ldmatrix.sync.aligned.m8n8.x4.trans.shared.b16 {%0,%1,%2,%3}, [%4];" \
                 : "=r"((R)[0]), "=r"((R)[1]), "=r"((R)[2]), "=r"((R)[3])     \
                 : "r"(addr))
#define MMA16816(d, a, b0, b1)                                                \
    asm volatile(                                                             \
        "mma.sync.aligned.m16n8k16.row.col.f32.f16.f16.f32 "                  \
        "{%0,%1,%2,%3}, {%4,%5,%6,%7}, {%8,%9}, {%0,%1,%2,%3};"               \
        : "+f"((d)[0]), "+f"((d)[1]), "+f"((d)[2]), "+f"((d)[3])              \
        : "r"((a)[0]), "r"((a)[1]), "r"((a)[2]), "r"((a)[3]),                 \
          "r"(b0), "r"(b1))

// ---------------------------------------------------------------------------
// Convert: fp32 -> fp16 (for W)
// ---------------------------------------------------------------------------
__global__ __launch_bounds__(256) void k_convert(
    const float* __restrict__ src, __half* __restrict__ dst, int n4)
{
    int i = blockIdx.x * blockDim.x + threadIdx.x;
    if (i >= n4) return;
    float4 v = ((const float4*)src)[i];
    ((__half2*)dst)[i * 2]     = __floats2half2_rn(v.x, v.y);
    ((__half2*)dst)[i * 2 + 1] = __floats2half2_rn(v.z, v.w);
}

// ---------------------------------------------------------------------------
// Fused: convert hs row -> fp16, and rank-1 projections a, c per row.
// ---------------------------------------------------------------------------
__global__ __launch_bounds__(256) void k_convert_proj(
    const float* __restrict__ hs, const float* __restrict__ U,
    const float* __restrict__ Vm, __half* __restrict__ dst)
{
    const int row = blockIdx.x;
    const int tid = threadIdx.x;
    __shared__ float redu[8], redv[8];

    int i = row * 256 + tid;
    float4 x = ((const float4*)hs)[i];
    ((__half2*)dst)[i * 2]     = __floats2half2_rn(x.x, x.y);
    ((__half2*)dst)[i * 2 + 1] = __floats2half2_rn(x.z, x.w);

    float4 u = ((const float4*)U)[tid];
    float4 v = ((const float4*)Vm)[tid];
    float su = x.x * u.x + x.y * u.y + x.z * u.z + x.w * u.w;
    float sv = x.x * v.x + x.y * v.y + x.z * v.z + x.w * v.w;
#pragma unroll
    for (int o = 16; o > 0; o >>= 1) {
        su += __shfl_xor_sync(0xFFFFFFFFu, su, o);
        sv += __shfl_xor_sync(0xFFFFFFFFu, sv, o);
    }
    if ((tid & 31) == 0) { redu[tid >> 5] = su; redv[tid >> 5] = sv; }
    __syncthreads();
    if (tid == 0) {
        float tu = 0.f, tv = 0.f;
#pragma unroll
        for (int w = 0; w < 8; w++) { tu += redu[w]; tv += redv[w]; }
        g_A[row] = (tu + U[H]) * 0.125f;
        g_C[row] = tv + Vm[H];
    }
}

// ---------------------------------------------------------------------------
// K1: fp16 mma.sync GEMM, fp16 output (+bias).
// CTA 128(M)x256(N), 8 warps, warp tile 64x64, BK=32, 3-stage cp.async.
// Row pitch 80B (conflict-free ldmatrix).
// ---------------------------------------------------------------------------
#define GBK 32
#define NKC (H / GBK)            // 32
#define NSTAGE 3
#define A_BYTES (128 * 80)       // 10240
#define B_BYTES (256 * 80)       // 20480
#define STG_BYTES (A_BYTES + B_BYTES)     // 30720
#define GEMM_SMEM (NSTAGE * STG_BYTES)    // 92160

__global__ __launch_bounds__(256, 1) void k_gemm_mma(
    const __half* __restrict__ Ah, const __half* __restrict__ Bh,
    const float* __restrict__ bias, __half* __restrict__ Cout)
{
    extern __shared__ char gsm[];
    const uint32_t smb = smem_u32(gsm);

    const int tid  = threadIdx.x;
    const int wid  = tid >> 5;
    const int lane = tid & 31;
    const int m0   = blockIdx.y * 128;
    const int n0   = blockIdx.x * 256;
    const int wm   = wid & 1;     // 2 m-subtiles of 64
    const int wn   = wid >> 1;    // 4 n-subtiles of 64

    const int ldrow = tid >> 2;   // 0..63
    const int ldc   = tid & 3;

    float acc[4][8][4];
#pragma unroll
    for (int i = 0; i < 4; i++)
#pragma unroll
        for (int j = 0; j < 8; j++)
#pragma unroll
            for (int q = 0; q < 4; q++) acc[i][j][q] = 0.f;

    auto load_stage = [&](int st, int kc) {
        const int k0 = kc * GBK;
        const uint32_t aB = smb + st * STG_BYTES;
        const uint32_t bB = aB + A_BYTES;
        uint32_t off = (uint32_t)ldrow * 80u + (uint32_t)ldc * 16u;
#pragma unroll
        for (int r = 0; r < 2; r++) {
            CPASYNC16(aB + off + r * (64 * 80),
                      Ah + (size_t)(m0 + ldrow + r * 64) * H + k0 + ldc * 8);
        }
#pragma unroll
        for (int r = 0; r < 4; r++) {
            CPASYNC16(bB + off + r * (64 * 80),
                      Bh + (size_t)(n0 + ldrow + r * 64) * H + k0 + ldc * 8);
        }
        CPCOMMIT();
    };

    load_stage(0, 0);
    load_stage(1, 1);

    for (int kc = 0; kc < NKC; kc++) {
        const int st = kc % NSTAGE;
        CPWAIT1();          // stage kc complete (kc+1 may be in flight)
        __syncthreads();    // all warps done with stage (kc+2)%NSTAGE buffer

        const int nk = kc + 2;
        if (nk < NKC) load_stage(nk % NSTAGE, nk);
        else          CPCOMMIT();

        const uint32_t aw = smb + st * STG_BYTES + (wm * 64) * 80;
        const uint32_t bw = smb + st * STG_BYTES + A_BYTES + (wn * 64) * 80;
        const uint32_t lrow = (lane & 15);
        const uint32_t lcol = (lane >> 4) * 16;

#pragma unroll
        for (int ks = 0; ks < 2; ks++) {
            const uint32_t kb = ks * 32 + lcol;
            uint32_t a[4][4];
#pragma unroll
            for (int i = 0; i < 4; i++)
                LDSM4(a[i], aw + (i * 16 + lrow) * 80 + kb);
#pragma unroll
            for (int jj = 0; jj < 4; jj++) {
                uint32_t r[4];
                LDSM4(r, bw + (jj * 16 + lrow) * 80 + kb);
#pragma unroll
                for (int i = 0; i < 4; i++) {
                    MMA16816(acc[i][jj * 2],     a[i], r[0], r[2]);
                    MMA16816(acc[i][jj * 2 + 1], a[i], r[1], r[3]);
                }
            }
        }
    }

    // Epilogue: fp16 stores with bias
#pragma unroll
    for (int j = 0; j < 8; j++) {
        int col = n0 + wn * 64 + j * 8 + (lane & 3) * 2;
        float b0 = bias[col], b1 = bias[col + 1];
#pragma unroll
        for (int i = 0; i < 4; i++) {
            int row = m0 + wm * 64 + i * 16 + (lane >> 2);
            *(__half2*)(Cout + (size_t)row * H + col) =
                __floats2half2_rn(acc[i][j][0] + b0, acc[i][j][1] + b1);
            *(__half2*)(Cout + (size_t)(row + 8) * H + col) =
                __floats2half2_rn(acc[i][j][2] + b0, acc[i][j][3] + b1);
        }
    }
}

// ---------------------------------------------------------------------------
// Merged bitonic sorts
// ---------------------------------------------------------------------------
__device__ __forceinline__ void bitonic_sort_2048(float* key, int* idx)
{
    for (int k = 2; k <= 2048; k <<= 1) {
        for (int j = k >> 1; j > 0; j >>= 1) {
#pragma unroll
            for (int p = 0; p < 2; p++) {
                int i = threadIdx.x + p * 1024;
                int l = i ^ j;
                if (l > i) {
                    bool up = ((i & k) == 0);
                    float ki = key[i], kl = key[l];
                    bool sw = up ? (ki > kl) : (ki < kl);
                    if (sw) {
                        key[i] = kl; key[l] = ki;
                        int t = idx[i]; idx[i] = idx[l]; idx[l] = t;
                    }
                }
            }
            __syncthreads();
        }
    }
}

__global__ __launch_bounds__(1024) void k_sorts(const float* __restrict__ mask)
{
    const int b    = blockIdx.x & 3;
    const int kind = blockIdx.x >> 2;
    __shared__ float key[2048];
    __shared__ int   idx[2048];
    const float* src = (kind == 0) ? g_C : g_A;
    for (int i = threadIdx.x; i < 2048; i += 1024) { key[i] = src[b * S + i]; idx[i] = i; }
    __syncthreads();
    bitonic_sort_2048(key, idx);
    if (kind == 0) {
        for (int i = threadIdx.x; i < 2048; i += 1024) {
            g_csort[b * S + i]    = key[i];
            g_cperm[b * S + i]    = idx[i];
            g_masksort[b * S + i] = mask[b * S + idx[i]];
        }
        __syncthreads();
        if (threadIdx.x < NCH) {
            int ch = threadIdx.x;
            float mm = -INFINITY;
            for (int j = 0; j < CHW; j++)
                mm = fmaxf(mm, mask[b * S + idx[ch * CHW + j]]);
            g_chmin[b * NCH + ch]  = key[ch * CHW];
            g_chmax[b * NCH + ch]  = key[ch * CHW + CHW - 1];
            g_chmmax[b * NCH + ch] = mm;
        }
    } else {
        for (int i = threadIdx.x; i < 2048; i += 1024) g_sperm[b * S + i] = idx[i];
    }
}

// ---------------------------------------------------------------------------
// K3: exact row max.  Warp per row.
// ---------------------------------------------------------------------------
__global__ __launch_bounds__(256) void k_max(const float* __restrict__ mask)
{
    const int row  = blockIdx.x * 8 + (threadIdx.x >> 5);
    const int b    = row >> 11;
    const int lane = threadIdx.x & 31;
    const float a  = g_A[row];
    const float* c  = g_C + (b << 11);
    const float* mk = mask + (b << 11);
    float m = -INFINITY;
    for (int t = lane; t < S; t += 32)
        m = fmaxf(m, fmaf(a, c[t], mk[t]));
#pragma unroll
    for (int o = 16; o > 0; o >>= 1)
        m = fmaxf(m, __shfl_xor_sync(0xFFFFFFFFu, m, o));
    if (lane == 0) g_m[row] = m;
}

// ---------------------------------------------------------------------------
// K4: sparse context on TENSOR CORES (R12 version — proven).
// ---------------------------------------------------------------------------
#define STILE 16
#define VPITCHH 520
#define VPITCHB (VPITCHH * 2)             // 1040 bytes
#define VHALF_BYTES (64 * VPITCHB)        // 66560
#define CTX_SMEM (2 * VHALF_BYTES)        // 133120

__global__ __launch_bounds__(256) void k_context_mma(float* __restrict__ out)
{
    extern __shared__ __align__(16) char vsm[];
    __shared__ __half Awt[16 * 72];
    __shared__ float wts[STILE][CHW];
    __shared__ float csh[CHW], msh[CHW];
    __shared__ int   psh[CHW];
    __shared__ float As[STILE], Ms[STILE], Zs[STILE];
    __shared__ int   rowid[STILE];
    __shared__ unsigned actmask;

    const int b    = blockIdx.y;
    const int tid  = threadIdx.x;
    const int wid  = tid >> 5;
    const int lane = tid & 31;

    const uint32_t vb0 = smem_u32(vsm);
    const uint32_t vb1 = vb0 + VHALF_BYTES;
    const uint32_t awb = smem_u32(Awt);

    if (tid < STILE) {
        int srow = g_sperm[b * S + blockIdx.x * STILE + tid];
        rowid[tid] = srow;
        As[tid] = g_A[b * S + srow];
        Ms[tid] = g_m[b * S + srow];
        Zs[tid] = 0.f;
    }

    float acc[2][8][4];
#pragma unroll
    for (int hh = 0; hh < 2; hh++)
#pragma unroll
        for (int j = 0; j < 8; j++)
#pragma unroll
            for (int q = 0; q < 4; q++) acc[hh][j][q] = 0.f;

    const int crow   = tid >> 6;
    const int cchunk = tid & 63;

    for (int ch = 0; ch < NCH; ch++) {
        __syncthreads();
        if (tid == 0) actmask = 0;
        __syncthreads();
        if (tid < STILE) {
            float a = As[tid];
            float cext = (a > 0.f) ? g_chmax[b * NCH + ch] : g_chmin[b * NCH + ch];
            float ub = fmaf(a, cext, g_chmmax[b * NCH + ch]) - Ms[tid];
            if (ub > -20.f) atomicOr(&actmask, 1u << tid);
        }
        __syncthreads();
        if (actmask == 0) continue;

        if (tid < CHW) {
            int g = b * S + ch * CHW + tid;
            csh[tid] = g_csort[g];
            msh[tid] = g_masksort[g];
            psh[tid] = g_cperm[g];
        }
        __syncthreads();

#pragma unroll 1
        for (int hh = 0; hh < 2; hh++) {
            const uint32_t dstb = (hh == 0) ? vb0 : vb1;
#pragma unroll
            for (int p = 0; p < 16; p++) {
                int row = crow + p * 4;
                const __half* src = g_valueh +
                    (((size_t)(b * S) + psh[row]) << 10) + hh * 512 + cchunk * 8;
                CPASYNC16(dstb + (uint32_t)row * VPITCHB + cchunk * 16, src);
            }
            CPCOMMIT();
        }

#pragma unroll
        for (int i = 0; i < (STILE * CHW) / 256; i++) {
            int idx = tid + i * 256;
            int si  = idx >> 6;
            int tj  = idx & (CHW - 1);
            float sc = fmaf(As[si], csh[tj], msh[tj]) - Ms[si];
            float w  = (sc > -25.f) ? __expf(sc) : 0.f;
            wts[si][tj] = w;
            Awt[si * 72 + tj] = __float2half(w);
        }
        __syncthreads();

        if (tid < STILE) {
            float z = 0.f;
#pragma unroll 8
            for (int j = 0; j < CHW; j++) z += wts[tid][j];
            Zs[tid] += z;
        }

        CPWAIT1();
        __syncthreads();

        uint32_t afr[4][4];
        {
            uint32_t abase = awb + (lane & 15) * 144 + (lane >> 4) * 16;
#pragma unroll
            for (int kk = 0; kk < 4; kk++)
                LDSM4(afr[kk], abase + kk * 32);
        }

#pragma unroll 1
        for (int hh = 0; hh < 2; hh++) {
            if (hh == 1) { CPWAIT0(); __syncthreads(); }
            const uint32_t vbh = (hh == 0) ? vb0 : vb1;
            const uint32_t bbase = vbh + (lane & 15) * VPITCHB +
                                   (wid * 64 + (lane >> 4) * 8) * 2;
#pragma unroll
            for (int kk = 0; kk < 4; kk++) {
                const uint32_t kadd = (uint32_t)(kk * 16) * VPITCHB;
#pragma unroll
                for (int jp = 0; jp < 4; jp++) {
                    uint32_t r[4];
                    LDSM4T(r, bbase + kadd + jp * 32);
                    MMA16816(acc[hh][jp * 2],     afr[kk], r[0], r[1]);
                    MMA16816(acc[hh][jp * 2 + 1], afr[kk], r[2], r[3]);
                }
            }
        }
    }
    __syncthreads();

    const int r1 = lane >> 2;
    const int r2 = r1 + 8;
    const float iz1 = 1.f / Zs[r1];
    const float iz2 = 1.f / Zs[r2];
    const size_t o1 = ((size_t)(b * S) + rowid[r1]) << 10;
    const size_t o2 = ((size_t)(b * S) + rowid[r2]) << 10;
#pragma unroll
    for (int hh = 0; hh < 2; hh++)
#pragma unroll
        for (int j = 0; j < 8; j++) {
            int col = hh * 512 + wid * 64 + j * 8 + (lane & 3) * 2;
            *(float2*)(out + o1 + col) =
                make_float2(acc[hh][j][0] * iz1, acc[hh][j][1] * iz1);
            *(float2*)(out + o2 + col) =
                make_float2(acc[hh][j][2] * iz2, acc[hh][j][3] * iz2);
        }
}

// ---------------------------------------------------------------------------
extern "C" void kernel_launch(void* const* d_in, const int* in_sizes, int n_in,
                              void* d_out, int out_size)
{
    const float* hs    = (const float*)d_in[0];  // [B,S,H]
    const float* mask  = (const float*)d_in[1];  // [B,S]
    const float* wv    = (const float*)d_in[2];  // [H,H]
    const float* bv    = (const float*)d_in[3];  // [H]
    const float* U     = (const float*)d_in[4];  // [H+1,1]
    const float* Vm    = (const float*)d_in[5];  // [1,H+1]
    float* out         = (float*)d_out;          // [B,S,H]

    __half* vproj = nullptr;
    cudaGetSymbolAddress((void**)&vproj, g_valueh);
    __half* ah = nullptr;
    cudaGetSymbolAddress((void**)&ah, g_Ah);
    __half* bh = nullptr;
    cudaGetSymbolAddress((void**)&bh, g_Bh);

    // conversions (+ fused rank-1 projections for hs)
    k_convert_proj<<<B * S, 256>>>(hs, U, Vm, ah);
    k_convert<<<(H * (H / 4) + 255) / 256, 256>>>(wv, bh, H * (H / 4));

    // K1: value projection via fp16 mma.sync (fp32 accumulate, fp16 out)
    cudaFuncSetAttribute(k_gemm_mma, cudaFuncAttributeMaxDynamicSharedMemorySize,
                         GEMM_SMEM);
    {
        dim3 grid(H / 256, (B * S) / 128);
        k_gemm_mma<<<grid, 256, GEMM_SMEM>>>(ah, bh, bv, vproj);
    }
    // merged sorts (c and a), then row maxima
    k_sorts<<<2 * B, 1024>>>(mask);
    k_max<<<(B * S) / 8, 256>>>(mask);
    // K4: sparse context on tensor cores
    cudaFuncSetAttribute(k_context_mma, cudaFuncAttributeMaxDynamicSharedMemorySize,
                         CTX_SMEM);
    {
        dim3 grid(S / STILE, B);
        k_context_mma<<<grid, 256, CTX_SMEM>>>(out);
    }
}

// round 14
// speedup vs baseline: 1.1719x; 1.1719x over previous
#include <cuda_runtime.h>
#include <cuda_fp16.h>
#include <math.h>
#include <stdint.h>

// Problem shape (fixed by dataset)
#define B 4
#define S 2048
#define H 1024
#define NCH 32          // chunks of 64 t per batch
#define CHW 64

// Scratch (device globals: no allocation allowed in kernel_launch)
__device__ __align__(16) __half g_valueh[B * S * H];  // value projection (fp16)
__device__ __align__(16) __half g_Ah[B * S * H];      // hs  as fp16
__device__ __align__(16) __half g_Bh[H * H];          // W   as fp16
__device__ float g_A[B * S];        // (x.U + U_H) / 8   per row
__device__ float g_C[B * S];        // x.V + V_H         per row
__device__ float g_m[B * S];        // row max of scores
__device__ float g_csort[B * S];    // c sorted ascending per batch
__device__ int   g_cperm[B * S];    // original t index per sorted position
__device__ float g_masksort[B * S]; // mask[cperm[j]]
__device__ int   g_sperm[B * S];    // s rows sorted by a per batch
__device__ float g_chmin[B * NCH];
__device__ float g_chmax[B * NCH];
__device__ float g_chmmax[B * NCH];

// ---------------------------------------------------------------------------
// PTX helpers
// ---------------------------------------------------------------------------
__device__ __forceinline__ uint32_t smem_u32(const void* p) {
    uint32_t a;
    asm("{ .reg .u64 t; cvta.to.shared.u64 t, %1; cvt.u32.u64 %0, t; }"
        : "=r"(a) : "l"(p));
    return a;
}
#define CPASYNC16(dst, src) \
    asm volatile("cp.async.cg.shared.global [%0], [%1], 16;" :: "r"(dst), "l"(src))
#define CPCOMMIT() asm volatile("cp.async.commit_group;" ::: "memory")
#define CPWAIT2()  asm volatile("cp.async.wait_group 2;" ::: "memory")
#define CPWAIT0()  asm volatile("cp.async.wait_group 0;" ::: "memory")
#define LDSM4(R, addr)                                                        \
    asm volatile("ldmatrix.sync.aligned.m8n8.x4.shared.b16 {%0,%1,%2,%3}, [%4];" \
                 : "=r"((R)[0]), "=r"((R)[1]), "=r"((R)[2]), "=r"((R)[3])     \
                 : "r"(addr))
#define LDSM4T(R, addr)                                                       \
    asm volatile("ldmatrix.sync.aligned.m8n8.x4.trans.shared.b16 {%0,%1,%2,%3}, [%4];" \
                 : "=r"((R)[0]), "=r"((R)[1]), "=r"((R)[2]), "=r"((R)[3])     \
                 : "r"(addr))
#define MMA16816(d, a, b0, b1)                                                \
    asm volatile(                                                             \
        "mma.sync.aligned.m16n8k16.row.col.f32.f16.f16.f32 "                  \
        "{%0,%1,%2,%3}, {%4,%5,%6,%7}, {%8,%9}, {%0,%1,%2,%3};"               \
        : "+f"((d)[0]), "+f"((d)[1]), "+f"((d)[2]), "+f"((d)[3])              \
        : "r"((a)[0]), "r"((a)[1]), "r"((a)[2]), "r"((a)[3]),                 \
          "r"(b0), "r"(b1))

// ---------------------------------------------------------------------------
// Convert: fp32 -> fp16 (for W)
// ---------------------------------------------------------------------------
__global__ __launch_bounds__(256) void k_convert(
    const float* __restrict__ src, __half* __restrict__ dst, int n4)
{
    int i = blockIdx.x * blockDim.x + threadIdx.x;
    if (i >= n4) return;
    float4 v = ((const float4*)src)[i];
    ((__half2*)dst)[i * 2]     = __floats2half2_rn(v.x, v.y);
    ((__half2*)dst)[i * 2 + 1] = __floats2half2_rn(v.z, v.w);
}

// ---------------------------------------------------------------------------
// Fused: convert hs row -> fp16, and rank-1 projections a, c per row.
// ---------------------------------------------------------------------------
__global__ __launch_bounds__(256) void k_convert_proj(
    const float* __restrict__ hs, const float* __restrict__ U,
    const float* __restrict__ Vm, __half* __restrict__ dst)
{
    const int row = blockIdx.x;
    const int tid = threadIdx.x;
    __shared__ float redu[8], redv[8];

    int i = row * 256 + tid;
    float4 x = ((const float4*)hs)[i];
    ((__half2*)dst)[i * 2]     = __floats2half2_rn(x.x, x.y);
    ((__half2*)dst)[i * 2 + 1] = __floats2half2_rn(x.z, x.w);

    float4 u = ((const float4*)U)[tid];
    float4 v = ((const float4*)Vm)[tid];
    float su = x.x * u.x + x.y * u.y + x.z * u.z + x.w * u.w;
    float sv = x.x * v.x + x.y * v.y + x.z * v.z + x.w * v.w;
#pragma unroll
    for (int o = 16; o > 0; o >>= 1) {
        su += __shfl_xor_sync(0xFFFFFFFFu, su, o);
        sv += __shfl_xor_sync(0xFFFFFFFFu, sv, o);
    }
    if ((tid & 31) == 0) { redu[tid >> 5] = su; redv[tid >> 5] = sv; }
    __syncthreads();
    if (tid == 0) {
        float tu = 0.f, tv = 0.f;
#pragma unroll
        for (int w = 0; w < 8; w++) { tu += redu[w]; tv += redv[w]; }
        g_A[row] = (tu + U[H]) * 0.125f;
        g_C[row] = tv + Vm[H];
    }
}

// ---------------------------------------------------------------------------
// K1: fp16 mma.sync GEMM (R12 config — proven). CTA 128x128, 8 warps,
// BK=32, 4-stage cp.async pipeline. Row pitch 80B.
// ---------------------------------------------------------------------------
#define GBK 32
#define NKC (H / GBK)           // 32
#define NSTAGE 4
#define MAT_BYTES (128 * 80)
#define STG_BYTES (2 * MAT_BYTES)
#define GEMM_SMEM (NSTAGE * STG_BYTES)  // 81920

__global__ __launch_bounds__(256, 2) void k_gemm_mma(
    const __half* __restrict__ Ah, const __half* __restrict__ Bh,
    const float* __restrict__ bias, __half* __restrict__ Cout)
{
    extern __shared__ char gsm[];
    const uint32_t smb = smem_u32(gsm);

    const int tid  = threadIdx.x;
    const int wid  = tid >> 5;
    const int lane = tid & 31;
    const int m0   = blockIdx.y * 128;
    const int n0   = blockIdx.x * 128;
    const int wm   = wid & 1;
    const int wn   = wid >> 1;

    const int ldrow = tid >> 2;
    const int ldc   = tid & 3;

    float acc[4][4][4];
#pragma unroll
    for (int i = 0; i < 4; i++)
#pragma unroll
        for (int j = 0; j < 4; j++)
#pragma unroll
            for (int q = 0; q < 4; q++) acc[i][j][q] = 0.f;

    auto load_stage = [&](int st, int kc) {
        const int k0 = kc * GBK;
        const uint32_t aB = smb + st * STG_BYTES;
        const uint32_t bB = aB + MAT_BYTES;
#pragma unroll
        for (int r = 0; r < 2; r++) {
            int row = ldrow + r * 64;
            uint32_t off = (uint32_t)row * 80u + (uint32_t)ldc * 16u;
            CPASYNC16(aB + off, Ah + (size_t)(m0 + row) * H + k0 + ldc * 8);
            CPASYNC16(bB + off, Bh + (size_t)(n0 + row) * H + k0 + ldc * 8);
        }
        CPCOMMIT();
    };

#pragma unroll
    for (int st = 0; st < NSTAGE - 1; st++) load_stage(st, st);

    for (int kc = 0; kc < NKC; kc++) {
        const int st = kc & (NSTAGE - 1);
        CPWAIT2();
        __syncthreads();

        const int nk = kc + NSTAGE - 1;
        if (nk < NKC) load_stage(nk & (NSTAGE - 1), nk);
        else          CPCOMMIT();

        const uint32_t aw = smb + st * STG_BYTES + (wm * 64) * 80;
        const uint32_t bw = smb + st * STG_BYTES + MAT_BYTES + (wn * 32) * 80;
        const uint32_t lrow = (lane & 15);
        const uint32_t lcol = (lane >> 4) * 16;

#pragma unroll
        for (int ks = 0; ks < 2; ks++) {
            const uint32_t kb = ks * 32 + lcol;
            uint32_t a[4][4];
#pragma unroll
            for (int i = 0; i < 4; i++)
                LDSM4(a[i], aw + (i * 16 + lrow) * 80 + kb);
            uint32_t br[2][4];
#pragma unroll
            for (int jj = 0; jj < 2; jj++)
                LDSM4(br[jj], bw + (jj * 16 + lrow) * 80 + kb);
#pragma unroll
            for (int i = 0; i < 4; i++) {
                MMA16816(acc[i][0], a[i], br[0][0], br[0][2]);
                MMA16816(acc[i][1], a[i], br[0][1], br[0][3]);
                MMA16816(acc[i][2], a[i], br[1][0], br[1][2]);
                MMA16816(acc[i][3], a[i], br[1][1], br[1][3]);
            }
        }
    }

#pragma unroll
    for (int j = 0; j < 4; j++) {
        int col = n0 + wn * 32 + j * 8 + (lane & 3) * 2;
        float b0 = bias[col], b1 = bias[col + 1];
#pragma unroll
        for (int i = 0; i < 4; i++) {
            int row = m0 + wm * 64 + i * 16 + (lane >> 2);
            *(__half2*)(Cout + (size_t)row * H + col) =
                __floats2half2_rn(acc[i][j][0] + b0, acc[i][j][1] + b1);
            *(__half2*)(Cout + (size_t)(row + 8) * H + col) =
                __floats2half2_rn(acc[i][j][2] + b0, acc[i][j][3] + b1);
        }
    }
}

// ---------------------------------------------------------------------------
// Merged bitonic sorts
// ---------------------------------------------------------------------------
__device__ __forceinline__ void bitonic_sort_2048(float* key, int* idx)
{
    for (int k = 2; k <= 2048; k <<= 1) {
        for (int j = k >> 1; j > 0; j >>= 1) {
#pragma unroll
            for (int p = 0; p < 2; p++) {
                int i = threadIdx.x + p * 1024;
                int l = i ^ j;
                if (l > i) {
                    bool up = ((i & k) == 0);
                    float ki = key[i], kl = key[l];
                    bool sw = up ? (ki > kl) : (ki < kl);
                    if (sw) {
                        key[i] = kl; key[l] = ki;
                        int t = idx[i]; idx[i] = idx[l]; idx[l] = t;
                    }
                }
            }
            __syncthreads();
        }
    }
}

__global__ __launch_bounds__(1024) void k_sorts(const float* __restrict__ mask)
{
    const int b    = blockIdx.x & 3;
    const int kind = blockIdx.x >> 2;
    __shared__ float key[2048];
    __shared__ int   idx[2048];
    const float* src = (kind == 0) ? g_C : g_A;
    for (int i = threadIdx.x; i < 2048; i += 1024) { key[i] = src[b * S + i]; idx[i] = i; }
    __syncthreads();
    bitonic_sort_2048(key, idx);
    if (kind == 0) {
        for (int i = threadIdx.x; i < 2048; i += 1024) {
            g_csort[b * S + i]    = key[i];
            g_cperm[b * S + i]    = idx[i];
            g_masksort[b * S + i] = mask[b * S + idx[i]];
        }
        __syncthreads();
        if (threadIdx.x < NCH) {
            int ch = threadIdx.x;
            float mm = -INFINITY;
            for (int j = 0; j < CHW; j++)
                mm = fmaxf(mm, mask[b * S + idx[ch * CHW + j]]);
            g_chmin[b * NCH + ch]  = key[ch * CHW];
            g_chmax[b * NCH + ch]  = key[ch * CHW + CHW - 1];
            g_chmmax[b * NCH + ch] = mm;
        }
    } else {
        for (int i = threadIdx.x; i < 2048; i += 1024) g_sperm[b * S + i] = idx[i];
    }
}

// ---------------------------------------------------------------------------
// K3: exact row max.  Warp per row.
// ---------------------------------------------------------------------------
__global__ __launch_bounds__(256) void k_max(const float* __restrict__ mask)
{
    const int row  = blockIdx.x * 8 + (threadIdx.x >> 5);
    const int b    = row >> 11;
    const int lane = threadIdx.x & 31;
    const float a  = g_A[row];
    const float* c  = g_C + (b << 11);
    const float* mk = mask + (b << 11);
    float m = -INFINITY;
    for (int t = lane; t < S; t += 32)
        m = fmaxf(m, fmaf(a, c[t], mk[t]));
#pragma unroll
    for (int o = 16; o > 0; o >>= 1)
        m = fmaxf(m, __shfl_xor_sync(0xFFFFFFFFu, m, o));
    if (lane == 0) g_m[row] = m;
}

// ---------------------------------------------------------------------------
// K4: sparse context on tensor cores. STILE=32 (two 16-row mma tiles),
// 512 threads (16 warps x 64 cols = full H in one pass). Per active chunk:
// stage 64 value rows (2048B each, pitch 2064 conflict-free) via cp.async.
// Halves total value staging traffic vs STILE=16.
// ---------------------------------------------------------------------------
#define STILE 32
#define VPITCHB 2064
#define CTX_SMEM (64 * VPITCHB)           // 132096

__global__ __launch_bounds__(512, 1) void k_context_mma(float* __restrict__ out)
{
    extern __shared__ __align__(16) char vsm[];
    __shared__ __half Awt[STILE * 72];     // A operand, pitch 72 halves (144B)
    __shared__ float wts[STILE][CHW];
    __shared__ float csh[CHW], msh[CHW];
    __shared__ int   psh[CHW];
    __shared__ float As[STILE], Ms[STILE], Zs[STILE];
    __shared__ int   rowid[STILE];
    __shared__ unsigned actmask;

    const int b    = blockIdx.y;
    const int tid  = threadIdx.x;
    const int wid  = tid >> 5;             // 0..15
    const int lane = tid & 31;

    const uint32_t vb  = smem_u32(vsm);
    const uint32_t awb = smem_u32(Awt);

    if (tid < STILE) {
        int srow = g_sperm[b * S + blockIdx.x * STILE + tid];
        rowid[tid] = srow;
        As[tid] = g_A[b * S + srow];
        Ms[tid] = g_m[b * S + srow];
        Zs[tid] = 0.f;
    }

    float acc[2][8][4];                    // [mtile][ntile][4]
#pragma unroll
    for (int mt = 0; mt < 2; mt++)
#pragma unroll
        for (int j = 0; j < 8; j++)
#pragma unroll
            for (int q = 0; q < 4; q++) acc[mt][j][q] = 0.f;

    const int crow   = tid >> 7;           // 4 rows per pass
    const int cchunk = tid & 127;          // 16B chunk within 2048B row

    for (int ch = 0; ch < NCH; ch++) {
        __syncthreads();
        if (tid == 0) actmask = 0;
        __syncthreads();
        if (tid < STILE) {
            float a = As[tid];
            float cext = (a > 0.f) ? g_chmax[b * NCH + ch] : g_chmin[b * NCH + ch];
            float ub = fmaf(a, cext, g_chmmax[b * NCH + ch]) - Ms[tid];
            if (ub > -20.f) atomicOr(&actmask, 1u << tid);
        }
        __syncthreads();
        if (actmask == 0) continue;

        if (tid < CHW) {
            int g = b * S + ch * CHW + tid;
            csh[tid] = g_csort[g];
            msh[tid] = g_masksort[g];
            psh[tid] = g_cperm[g];
        }
        __syncthreads();

        // stage 64 value rows (full 1024 cols each)
#pragma unroll
        for (int p = 0; p < 16; p++) {
            int row = crow + p * 4;
            const __half* src = g_valueh +
                (((size_t)(b * S) + psh[row]) << 10) + cchunk * 8;
            CPASYNC16(vb + (uint32_t)row * VPITCHB + cchunk * 16, src);
        }
        CPCOMMIT();

        // weights: 32 x 64 = 2048 entries, 4 per thread
#pragma unroll
        for (int i = 0; i < (STILE * CHW) / 512; i++) {
            int idx = tid + i * 512;
            int si  = idx >> 6;
            int tj  = idx & (CHW - 1);
            float sc = fmaf(As[si], csh[tj], msh[tj]) - Ms[si];
            float w  = (sc > -25.f) ? __expf(sc) : 0.f;
            wts[si][tj] = w;
            Awt[si * 72 + tj] = __float2half(w);
        }
        __syncthreads();

        if (tid < STILE) {
            float z = 0.f;
#pragma unroll 8
            for (int j = 0; j < CHW; j++) z += wts[tid][j];
            Zs[tid] += z;
        }

        CPWAIT0();
        __syncthreads();

        const uint32_t abase = awb + (lane & 15) * 144 + (lane >> 4) * 16;
        const uint32_t bbase = vb + (lane & 15) * VPITCHB +
                               (wid * 64 + (lane >> 4) * 8) * 2;
#pragma unroll
        for (int kk = 0; kk < 4; kk++) {
            uint32_t a0[4], a1[4];
            LDSM4(a0, abase + kk * 32);
            LDSM4(a1, abase + 16 * 144 + kk * 32);
            const uint32_t kadd = (uint32_t)(kk * 16) * VPITCHB;
#pragma unroll
            for (int jp = 0; jp < 4; jp++) {
                uint32_t r[4];
                LDSM4T(r, bbase + kadd + jp * 32);
                MMA16816(acc[0][jp * 2],     a0, r[0], r[1]);
                MMA16816(acc[0][jp * 2 + 1], a0, r[2], r[3]);
                MMA16816(acc[1][jp * 2],     a1, r[0], r[1]);
                MMA16816(acc[1][jp * 2 + 1], a1, r[2], r[3]);
            }
        }
    }
    __syncthreads();

    // epilogue
#pragma unroll
    for (int mt = 0; mt < 2; mt++) {
        const int r1 = mt * 16 + (lane >> 2);
        const int r2 = r1 + 8;
        const float iz1 = 1.f / Zs[r1];
        const float iz2 = 1.f / Zs[r2];
        const size_t o1 = ((size_t)(b * S) + rowid[r1]) << 10;
        const size_t o2 = ((size_t)(b * S) + rowid[r2]) << 10;
#pragma unroll
        for (int j = 0; j < 8; j++) {
            int col = wid * 64 + j * 8 + (lane & 3) * 2;
            *(float2*)(out + o1 + col) =
                make_float2(acc[mt][j][0] * iz1, acc[mt][j][1] * iz1);
            *(float2*)(out + o2 + col) =
                make_float2(acc[mt][j][2] * iz2, acc[mt][j][3] * iz2);
        }
    }
}

// ---------------------------------------------------------------------------
extern "C" void kernel_launch(void* const* d_in, const int* in_sizes, int n_in,
                              void* d_out, int out_size)
{
    const float* hs    = (const float*)d_in[0];  // [B,S,H]
    const float* mask  = (const float*)d_in[1];  // [B,S]
    const float* wv    = (const float*)d_in[2];  // [H,H]
    const float* bv    = (const float*)d_in[3];  // [H]
    const float* U     = (const float*)d_in[4];  // [H+1,1]
    const float* Vm    = (const float*)d_in[5];  // [1,H+1]
    float* out         = (float*)d_out;          // [B,S,H]

    __half* vproj = nullptr;
    cudaGetSymbolAddress((void**)&vproj, g_valueh);
    __half* ah = nullptr;
    cudaGetSymbolAddress((void**)&ah, g_Ah);
    __half* bh = nullptr;
    cudaGetSymbolAddress((void**)&bh, g_Bh);

    // conversions (+ fused rank-1 projections for hs)
    k_convert_proj<<<B * S, 256>>>(hs, U, Vm, ah);
    k_convert<<<(H * (H / 4) + 255) / 256, 256>>>(wv, bh, H * (H / 4));

    // K1: value projection via fp16 mma.sync (fp32 accumulate, fp16 out)
    cudaFuncSetAttribute(k_gemm_mma, cudaFuncAttributeMaxDynamicSharedMemorySize,
                         GEMM_SMEM);
    {
        dim3 grid(H / 128, (B * S) / 128);
        k_gemm_mma<<<grid, 256, GEMM_SMEM>>>(ah, bh, bv, vproj);
    }
    // merged sorts (c and a), then row maxima
    k_sorts<<<2 * B, 1024>>>(mask);
    k_max<<<(B * S) / 8, 256>>>(mask);
    // K4: sparse context on tensor cores (STILE=32)
    cudaFuncSetAttribute(k_context_mma, cudaFuncAttributeMaxDynamicSharedMemorySize,
                         CTX_SMEM);
    {
        dim3 grid(S / STILE, B);
        k_context_mma<<<grid, 512, CTX_SMEM>>>(out);
    }
}

// round 15
// speedup vs baseline: 1.3309x; 1.1357x over previous
#include <cuda_runtime.h>
#include <cuda_fp16.h>
#include <math.h>
#include <stdint.h>

// Problem shape (fixed by dataset)
#define B 4
#define S 2048
#define H 1024
#define NCH 32          // chunks of 64 t per batch
#define CHW 64

// Scratch (device globals: no allocation allowed in kernel_launch)
__device__ __align__(16) __half g_valueh[B * S * H];  // value projection (fp16)
__device__ __align__(16) __half g_Ah[B * S * H];      // hs  as fp16
__device__ __align__(16) __half g_Bh[H * H];          // W   as fp16
__device__ float g_A[B * S];        // (x.U + U_H) / 8   per row
__device__ float g_C[B * S];        // x.V + V_H         per row
__device__ float g_m[B * S];        // row max of scores
__device__ float g_csort[B * S];    // c sorted ascending per batch
__device__ int   g_cperm[B * S];    // original t index per sorted position
__device__ float g_masksort[B * S]; // mask[cperm[j]]
__device__ int   g_sperm[B * S];    // s rows sorted by a per batch
__device__ float g_chmin[B * NCH];
__device__ float g_chmax[B * NCH];
__device__ float g_chmmax[B * NCH];

// ---------------------------------------------------------------------------
// PTX helpers
// ---------------------------------------------------------------------------
__device__ __forceinline__ uint32_t smem_u32(const void* p) {
    uint32_t a;
    asm("{ .reg .u64 t; cvta.to.shared.u64 t, %1; cvt.u32.u64 %0, t; }"
        : "=r"(a) : "l"(p));
    return a;
}
#define CPASYNC16(dst, src) \
    asm volatile("cp.async.cg.shared.global [%0], [%1], 16;" :: "r"(dst), "l"(src))
#define CPCOMMIT() asm volatile("cp.async.commit_group;" ::: "memory")
#define CPWAIT2()  asm volatile("cp.async.wait_group 2;" ::: "memory")
#define CPWAIT0()  asm volatile("cp.async.wait_group 0;" ::: "memory")
#define LDSM4(R, addr)                                                        \
    asm volatile("ldmatrix.sync.aligned.m8n8.x4.shared.b16 {%0,%1,%2,%3}, [%4];" \
                 : "=r"((R)[0]), "=r"((R)[1]), "=r"((R)[2]), "=r"((R)[3])     \
                 : "r"(addr))
#define LDSM4T(R, addr)                                                       \
    asm volatile("ldmatrix.sync.aligned.m8n8.x4.trans.shared.b16 {%0,%1,%2,%3}, [%4];" \
                 : "=r"((R)[0]), "=r"((R)[1]), "=r"((R)[2]), "=r"((R)[3])     \
                 : "r"(addr))
#define MMA16816(d, a, b0, b1)                                                \
    asm volatile(                                                             \
        "mma.sync.aligned.m16n8k16.row.col.f32.f16.f16.f32 "                  \
        "{%0,%1,%2,%3}, {%4,%5,%6,%7}, {%8,%9}, {%0,%1,%2,%3};"               \
        : "+f"((d)[0]), "+f"((d)[1]), "+f"((d)[2]), "+f"((d)[3])              \
        : "r"((a)[0]), "r"((a)[1]), "r"((a)[2]), "r"((a)[3]),                 \
          "r"(b0), "r"(b1))

// ---------------------------------------------------------------------------
// Convert: fp32 -> fp16 (for W)
// ---------------------------------------------------------------------------
__global__ __launch_bounds__(256) void k_convert(
    const float* __restrict__ src, __half* __restrict__ dst, int n4)
{
    int i = blockIdx.x * blockDim.x + threadIdx.x;
    if (i >= n4) return;
    float4 v = ((const float4*)src)[i];
    ((__half2*)dst)[i * 2]     = __floats2half2_rn(v.x, v.y);
    ((__half2*)dst)[i * 2 + 1] = __floats2half2_rn(v.z, v.w);
}

// ---------------------------------------------------------------------------
// Fused: convert hs row -> fp16, and rank-1 projections a, c per row.
// ---------------------------------------------------------------------------
__global__ __launch_bounds__(256) void k_convert_proj(
    const float* __restrict__ hs, const float* __restrict__ U,
    const float* __restrict__ Vm, __half* __restrict__ dst)
{
    const int row = blockIdx.x;
    const int tid = threadIdx.x;
    __shared__ float redu[8], redv[8];

    int i = row * 256 + tid;
    float4 x = ((const float4*)hs)[i];
    ((__half2*)dst)[i * 2]     = __floats2half2_rn(x.x, x.y);
    ((__half2*)dst)[i * 2 + 1] = __floats2half2_rn(x.z, x.w);

    float4 u = ((const float4*)U)[tid];
    float4 v = ((const float4*)Vm)[tid];
    float su = x.x * u.x + x.y * u.y + x.z * u.z + x.w * u.w;
    float sv = x.x * v.x + x.y * v.y + x.z * v.z + x.w * v.w;
#pragma unroll
    for (int o = 16; o > 0; o >>= 1) {
        su += __shfl_xor_sync(0xFFFFFFFFu, su, o);
        sv += __shfl_xor_sync(0xFFFFFFFFu, sv, o);
    }
    if ((tid & 31) == 0) { redu[tid >> 5] = su; redv[tid >> 5] = sv; }
    __syncthreads();
    if (tid == 0) {
        float tu = 0.f, tv = 0.f;
#pragma unroll
        for (int w = 0; w < 8; w++) { tu += redu[w]; tv += redv[w]; }
        g_A[row] = (tu + U[H]) * 0.125f;
        g_C[row] = tv + Vm[H];
    }
}

// ---------------------------------------------------------------------------
// K1: fp16 mma.sync GEMM (proven config). CTA 128x128, 8 warps,
// BK=32, 4-stage cp.async pipeline. Row pitch 80B.
// ---------------------------------------------------------------------------
#define GBK 32
#define NKC (H / GBK)           // 32
#define NSTAGE 4
#define MAT_BYTES (128 * 80)
#define STG_BYTES (2 * MAT_BYTES)
#define GEMM_SMEM (NSTAGE * STG_BYTES)  // 81920

__global__ __launch_bounds__(256, 2) void k_gemm_mma(
    const __half* __restrict__ Ah, const __half* __restrict__ Bh,
    const float* __restrict__ bias, __half* __restrict__ Cout)
{
    extern __shared__ char gsm[];
    const uint32_t smb = smem_u32(gsm);

    const int tid  = threadIdx.x;
    const int wid  = tid >> 5;
    const int lane = tid & 31;
    const int m0   = blockIdx.y * 128;
    const int n0   = blockIdx.x * 128;
    const int wm   = wid & 1;
    const int wn   = wid >> 1;

    const int ldrow = tid >> 2;
    const int ldc   = tid & 3;

    float acc[4][4][4];
#pragma unroll
    for (int i = 0; i < 4; i++)
#pragma unroll
        for (int j = 0; j < 4; j++)
#pragma unroll
            for (int q = 0; q < 4; q++) acc[i][j][q] = 0.f;

    auto load_stage = [&](int st, int kc) {
        const int k0 = kc * GBK;
        const uint32_t aB = smb + st * STG_BYTES;
        const uint32_t bB = aB + MAT_BYTES;
#pragma unroll
        for (int r = 0; r < 2; r++) {
            int row = ldrow + r * 64;
            uint32_t off = (uint32_t)row * 80u + (uint32_t)ldc * 16u;
            CPASYNC16(aB + off, Ah + (size_t)(m0 + row) * H + k0 + ldc * 8);
            CPASYNC16(bB + off, Bh + (size_t)(n0 + row) * H + k0 + ldc * 8);
        }
        CPCOMMIT();
    };

#pragma unroll
    for (int st = 0; st < NSTAGE - 1; st++) load_stage(st, st);

    for (int kc = 0; kc < NKC; kc++) {
        const int st = kc & (NSTAGE - 1);
        CPWAIT2();
        __syncthreads();

        const int nk = kc + NSTAGE - 1;
        if (nk < NKC) load_stage(nk & (NSTAGE - 1), nk);
        else          CPCOMMIT();

        const uint32_t aw = smb + st * STG_BYTES + (wm * 64) * 80;
        const uint32_t bw = smb + st * STG_BYTES + MAT_BYTES + (wn * 32) * 80;
        const uint32_t lrow = (lane & 15);
        const uint32_t lcol = (lane >> 4) * 16;

#pragma unroll
        for (int ks = 0; ks < 2; ks++) {
            const uint32_t kb = ks * 32 + lcol;
            uint32_t a[4][4];
#pragma unroll
            for (int i = 0; i < 4; i++)
                LDSM4(a[i], aw + (i * 16 + lrow) * 80 + kb);
            uint32_t br[2][4];
#pragma unroll
            for (int jj = 0; jj < 2; jj++)
                LDSM4(br[jj], bw + (jj * 16 + lrow) * 80 + kb);
#pragma unroll
            for (int i = 0; i < 4; i++) {
                MMA16816(acc[i][0], a[i], br[0][0], br[0][2]);
                MMA16816(acc[i][1], a[i], br[0][1], br[0][3]);
                MMA16816(acc[i][2], a[i], br[1][0], br[1][2]);
                MMA16816(acc[i][3], a[i], br[1][1], br[1][3]);
            }
        }
    }

#pragma unroll
    for (int j = 0; j < 4; j++) {
        int col = n0 + wn * 32 + j * 8 + (lane & 3) * 2;
        float b0 = bias[col], b1 = bias[col + 1];
#pragma unroll
        for (int i = 0; i < 4; i++) {
            int row = m0 + wm * 64 + i * 16 + (lane >> 2);
            *(__half2*)(Cout + (size_t)row * H + col) =
                __floats2half2_rn(acc[i][j][0] + b0, acc[i][j][1] + b1);
            *(__half2*)(Cout + (size_t)(row + 8) * H + col) =
                __floats2half2_rn(acc[i][j][2] + b0, acc[i][j][3] + b1);
        }
    }
}

// ---------------------------------------------------------------------------
// Merged bitonic sorts
// ---------------------------------------------------------------------------
__device__ __forceinline__ void bitonic_sort_2048(float* key, int* idx)
{
    for (int k = 2; k <= 2048; k <<= 1) {
        for (int j = k >> 1; j > 0; j >>= 1) {
#pragma unroll
            for (int p = 0; p < 2; p++) {
                int i = threadIdx.x + p * 1024;
                int l = i ^ j;
                if (l > i) {
                    bool up = ((i & k) == 0);
                    float ki = key[i], kl = key[l];
                    bool sw = up ? (ki > kl) : (ki < kl);
                    if (sw) {
                        key[i] = kl; key[l] = ki;
                        int t = idx[i]; idx[i] = idx[l]; idx[l] = t;
                    }
                }
            }
            __syncthreads();
        }
    }
}

__global__ __launch_bounds__(1024) void k_sorts(const float* __restrict__ mask)
{
    const int b    = blockIdx.x & 3;
    const int kind = blockIdx.x >> 2;
    __shared__ float key[2048];
    __shared__ int   idx[2048];
    const float* src = (kind == 0) ? g_C : g_A;
    for (int i = threadIdx.x; i < 2048; i += 1024) { key[i] = src[b * S + i]; idx[i] = i; }
    __syncthreads();
    bitonic_sort_2048(key, idx);
    if (kind == 0) {
        for (int i = threadIdx.x; i < 2048; i += 1024) {
            g_csort[b * S + i]    = key[i];
            g_cperm[b * S + i]    = idx[i];
            g_masksort[b * S + i] = mask[b * S + idx[i]];
        }
        __syncthreads();
        if (threadIdx.x < NCH) {
            int ch = threadIdx.x;
            float mm = -INFINITY;
            for (int j = 0; j < CHW; j++)
                mm = fmaxf(mm, mask[b * S + idx[ch * CHW + j]]);
            g_chmin[b * NCH + ch]  = key[ch * CHW];
            g_chmax[b * NCH + ch]  = key[ch * CHW + CHW - 1];
            g_chmmax[b * NCH + ch] = mm;
        }
    } else {
        for (int i = threadIdx.x; i < 2048; i += 1024) g_sperm[b * S + i] = idx[i];
    }
}

// ---------------------------------------------------------------------------
// K3: exact row max.  Warp per row.
// ---------------------------------------------------------------------------
__global__ __launch_bounds__(256) void k_max(const float* __restrict__ mask)
{
    const int row  = blockIdx.x * 8 + (threadIdx.x >> 5);
    const int b    = row >> 11;
    const int lane = threadIdx.x & 31;
    const float a  = g_A[row];
    const float* c  = g_C + (b << 11);
    const float* mk = mask + (b << 11);
    float m = -INFINITY;
    for (int t = lane; t < S; t += 32)
        m = fmaxf(m, fmaf(a, c[t], mk[t]));
#pragma unroll
    for (int o = 16; o > 0; o >>= 1)
        m = fmaxf(m, __shfl_xor_sync(0xFFFFFFFFu, m, o));
    if (lane == 0) g_m[row] = m;
}

// ---------------------------------------------------------------------------
// K4: sparse context on tensor cores. STILE=32, 512 threads (16 warps x
// 64 cols = full H). Stage 64 value rows per active chunk via cp.async.
// ---------------------------------------------------------------------------
#define STILE 32
#define VPITCHB 2064
#define CTX_SMEM (64 * VPITCHB)           // 132096

__global__ __launch_bounds__(512, 1) void k_context_mma(float* __restrict__ out)
{
    extern __shared__ __align__(16) char vsm[];
    __shared__ __half Awt[STILE * 72];
    __shared__ float wts[STILE][CHW];
    __shared__ float csh[CHW], msh[CHW];
    __shared__ int   psh[CHW];
    __shared__ float As[STILE], Ms[STILE], Zs[STILE];
    __shared__ int   rowid[STILE];
    __shared__ unsigned actmask;

    const int b    = blockIdx.y;
    const int tid  = threadIdx.x;
    const int wid  = tid >> 5;
    const int lane = tid & 31;

    const uint32_t vb  = smem_u32(vsm);
    const uint32_t awb = smem_u32(Awt);

    if (tid < STILE) {
        int srow = g_sperm[b * S + blockIdx.x * STILE + tid];
        rowid[tid] = srow;
        As[tid] = g_A[b * S + srow];
        Ms[tid] = g_m[b * S + srow];
        Zs[tid] = 0.f;
    }

    float acc[2][8][4];
#pragma unroll
    for (int mt = 0; mt < 2; mt++)
#pragma unroll
        for (int j = 0; j < 8; j++)
#pragma unroll
            for (int q = 0; q < 4; q++) acc[mt][j][q] = 0.f;

    const int crow   = tid >> 7;
    const int cchunk = tid & 127;

    for (int ch = 0; ch < NCH; ch++) {
        __syncthreads();
        if (tid == 0) actmask = 0;
        __syncthreads();
        if (tid < STILE) {
            float a = As[tid];
            float cext = (a > 0.f) ? g_chmax[b * NCH + ch] : g_chmin[b * NCH + ch];
            float ub = fmaf(a, cext, g_chmmax[b * NCH + ch]) - Ms[tid];
            if (ub > -20.f) atomicOr(&actmask, 1u << tid);
        }
        __syncthreads();
        if (actmask == 0) continue;

        if (tid < CHW) {
            int g = b * S + ch * CHW + tid;
            csh[tid] = g_csort[g];
            msh[tid] = g_masksort[g];
            psh[tid] = g_cperm[g];
        }
        __syncthreads();

#pragma unroll
        for (int p = 0; p < 16; p++) {
            int row = crow + p * 4;
            const __half* src = g_valueh +
                (((size_t)(b * S) + psh[row]) << 10) + cchunk * 8;
            CPASYNC16(vb + (uint32_t)row * VPITCHB + cchunk * 16, src);
        }
        CPCOMMIT();

#pragma unroll
        for (int i = 0; i < (STILE * CHW) / 512; i++) {
            int idx = tid + i * 512;
            int si  = idx >> 6;
            int tj  = idx & (CHW - 1);
            float sc = fmaf(As[si], csh[tj], msh[tj]) - Ms[si];
            float w  = (sc > -25.f) ? __expf(sc) : 0.f;
            wts[si][tj] = w;
            Awt[si * 72 + tj] = __float2half(w);
        }
        __syncthreads();

        if (tid < STILE) {
            float z = 0.f;
#pragma unroll 8
            for (int j = 0; j < CHW; j++) z += wts[tid][j];
            Zs[tid] += z;
        }

        CPWAIT0();
        __syncthreads();

        const uint32_t abase = awb + (lane & 15) * 144 + (lane >> 4) * 16;
        const uint32_t bbase = vb + (lane & 15) * VPITCHB +
                               (wid * 64 + (lane >> 4) * 8) * 2;
#pragma unroll
        for (int kk = 0; kk < 4; kk++) {
            uint32_t a0[4], a1[4];
            LDSM4(a0, abase + kk * 32);
            LDSM4(a1, abase + 16 * 144 + kk * 32);
            const uint32_t kadd = (uint32_t)(kk * 16) * VPITCHB;
#pragma unroll
            for (int jp = 0; jp < 4; jp++) {
                uint32_t r[4];
                LDSM4T(r, bbase + kadd + jp * 32);
                MMA16816(acc[0][jp * 2],     a0, r[0], r[1]);
                MMA16816(acc[0][jp * 2 + 1], a0, r[2], r[3]);
                MMA16816(acc[1][jp * 2],     a1, r[0], r[1]);
                MMA16816(acc[1][jp * 2 + 1], a1, r[2], r[3]);
            }
        }
    }
    __syncthreads();

#pragma unroll
    for (int mt = 0; mt < 2; mt++) {
        const int r1 = mt * 16 + (lane >> 2);
        const int r2 = r1 + 8;
        const float iz1 = 1.f / Zs[r1];
        const float iz2 = 1.f / Zs[r2];
        const size_t o1 = ((size_t)(b * S) + rowid[r1]) << 10;
        const size_t o2 = ((size_t)(b * S) + rowid[r2]) << 10;
#pragma unroll
        for (int j = 0; j < 8; j++) {
            int col = wid * 64 + j * 8 + (lane & 3) * 2;
            *(float2*)(out + o1 + col) =
                make_float2(acc[mt][j][0] * iz1, acc[mt][j][1] * iz1);
            *(float2*)(out + o2 + col) =
                make_float2(acc[mt][j][2] * iz2, acc[mt][j][3] * iz2);
        }
    }
}

// ---------------------------------------------------------------------------
extern "C" void kernel_launch(void* const* d_in, const int* in_sizes, int n_in,
                              void* d_out, int out_size)
{
    const float* hs    = (const float*)d_in[0];  // [B,S,H]
    const float* mask  = (const float*)d_in[1];  // [B,S]
    const float* wv    = (const float*)d_in[2];  // [H,H]
    const float* bv    = (const float*)d_in[3];  // [H]
    const float* U     = (const float*)d_in[4];  // [H+1,1]
    const float* Vm    = (const float*)d_in[5];  // [1,H+1]
    float* out         = (float*)d_out;          // [B,S,H]

    __half* vproj = nullptr;
    cudaGetSymbolAddress((void**)&vproj, g_valueh);
    __half* ah = nullptr;
    cudaGetSymbolAddress((void**)&ah, g_Ah);
    __half* bh = nullptr;
    cudaGetSymbolAddress((void**)&bh, g_Bh);

    cudaFuncSetAttribute(k_gemm_mma, cudaFuncAttributeMaxDynamicSharedMemorySize,
                         GEMM_SMEM);
    cudaFuncSetAttribute(k_context_mma, cudaFuncAttributeMaxDynamicSharedMemorySize,
                         CTX_SMEM);

    // side stream + events for fork/join (host objects only; intentionally
    // not destroyed — kernel_launch runs only a handful of times, and the
    // captured graph references them)
    cudaStream_t side;
    cudaEvent_t ev1, ev2;
    bool forked = (cudaStreamCreateWithFlags(&side, cudaStreamNonBlocking) == cudaSuccess)
               && (cudaEventCreateWithFlags(&ev1, cudaEventDisableTiming) == cudaSuccess)
               && (cudaEventCreateWithFlags(&ev2, cudaEventDisableTiming) == cudaSuccess);

    // main: conversions (+ fused rank-1 projections for hs)
    k_convert_proj<<<B * S, 256>>>(hs, U, Vm, ah);
    k_convert<<<(H * (H / 4) + 255) / 256, 256>>>(wv, bh, H * (H / 4));

    if (forked) forked = (cudaEventRecord(ev1, 0) == cudaSuccess) &&
                         (cudaStreamWaitEvent(side, ev1, 0) == cudaSuccess);

    if (forked) {
        // side branch: sorts + row maxima (independent of the GEMM)
        k_sorts<<<2 * B, 1024, 0, side>>>(mask);
        k_max<<<(B * S) / 8, 256, 0, side>>>(mask);
        cudaEventRecord(ev2, side);

        // main branch: value-projection GEMM
        dim3 grid(H / 128, (B * S) / 128);
        k_gemm_mma<<<grid, 256, GEMM_SMEM>>>(ah, bh, bv, vproj);

        cudaStreamWaitEvent(0, ev2, 0);
    } else {
        // serial fallback
        dim3 grid(H / 128, (B * S) / 128);
        k_gemm_mma<<<grid, 256, GEMM_SMEM>>>(ah, bh, bv, vproj);
        k_sorts<<<2 * B, 1024>>>(mask);
        k_max<<<(B * S) / 8, 256>>>(mask);
    }

    // join: sparse context on tensor cores (needs GEMM + sorts + max)
    {
        dim3 grid(S / STILE, B);
        k_context_mma<<<grid, 512, CTX_SMEM>>>(out);
    }
}